// round 3
// baseline (speedup 1.0000x reference)
#include <cuda_runtime.h>
#include <cuda_bf16.h>

// Problem dims (fixed by the reference):
// B=2, G=8, D=32, H=128, W=160, NEIGH=9 (3x3), PAD1=2, PAD2=4
#define B_  2
#define G_  8
#define D_  32
#define H_  128
#define W_  160
#define HW_ (H_*W_)          // 20480
#define DHW_ (D_*HW_)        // 655360
#define N1_ (B_*DHW_)        // 1310720  (sim / output elements)

// Scratch for the per-pixel similarity map (B, D, H, W) fp32 = 5.24 MB
__device__ float g_sim[N1_];

// ---------------------------------------------------------------------------
// Kernel 1: per-pixel MLP  sim = w_sim . relu( bn1(W1 . relu( bn0(W0 . x) )) ) + b_sim
// One thread per (b,d,h,w). x gathered across G with stride DHW.
// ---------------------------------------------------------------------------
__global__ __launch_bounds__(256)
void mlp_sim_kernel(const float* __restrict__ x1,
                    const float* __restrict__ w0,
                    const float* __restrict__ bn0_scale,
                    const float* __restrict__ bn0_bias,
                    const float* __restrict__ w1,
                    const float* __restrict__ bn1_scale,
                    const float* __restrict__ bn1_bias,
                    const float* __restrict__ w_sim,
                    const float* __restrict__ b_sim)
{
    __shared__ float sw0[16*8];   // w0[o][g] * bn0_scale[o]
    __shared__ float sb0[16];
    __shared__ float sw1[8*16];   // w1[k][o] * bn1_scale[k]
    __shared__ float sb1[8];
    __shared__ float sws[8];
    __shared__ float sbs;

    const int t = threadIdx.x;
    if (t < 128) {
        sw0[t] = w0[t] * bn0_scale[t >> 3];
    } else {
        int i = t - 128;               // 0..127
        sw1[i] = w1[i] * bn1_scale[i >> 4];
    }
    if (t < 16)       sb0[t] = bn0_bias[t];
    else if (t < 24)  sb1[t - 16] = bn1_bias[t - 16];
    else if (t < 32)  sws[t - 24] = w_sim[t - 24];
    else if (t == 32) sbs = b_sim[0];
    __syncthreads();

    const int idx = blockIdx.x * 256 + t;          // N1_ is a multiple of 256
    const int b = idx / DHW_;
    // x1 index of (b, g=0, d, h, w):  idx + b*(G-1)*DHW
    const long base = (long)idx + (long)b * (long)(G_ - 1) * DHW_;

    float x[G_];
#pragma unroll
    for (int g = 0; g < G_; g++)
        x[g] = __ldg(&x1[base + (long)g * DHW_]);

    float h1[8];
#pragma unroll
    for (int k = 0; k < 8; k++) h1[k] = sb1[k];

#pragma unroll
    for (int o = 0; o < 16; o++) {
        float a = sb0[o];
#pragma unroll
        for (int g = 0; g < G_; g++)
            a = fmaf(sw0[o * 8 + g], x[g], a);
        a = fmaxf(a, 0.0f);
#pragma unroll
        for (int k = 0; k < 8; k++)
            h1[k] = fmaf(sw1[k * 16 + o], a, h1[k]);
    }

    float sim = sbs;
#pragma unroll
    for (int k = 0; k < 8; k++)
        sim = fmaf(sws[k], fmaxf(h1[k], 0.0f), sim);

    g_sim[idx] = sim;
}

// ---------------------------------------------------------------------------
// Kernel 2: two-scale 3x3 reflect stencil over sim, weighted by offset maps.
// out[b,d,h,w] = 0.5 * weight[b,h,w] *
//   sum_{iy,ix} ( offset[b, s+9, h, w] * sim[b,d, r(h+2(iy-1)), r(w+2(ix-1))]
//               + offset[b, s,   h, w] * sim[b,d, r(h+4(iy-1)), r(w+4(ix-1))] )
// One thread per (b, d-chunk of 4, h, w); loops 4 d-slices.
// ---------------------------------------------------------------------------
#define DCHUNK 4

__device__ __forceinline__ int reflect_idx(int k, int n) {
    // single reflection is sufficient: |k| <= 4 out of range, n >= 128
    if (k < 0) return -k;
    if (k >= n) return 2 * n - 2 - k;
    return k;
}

__global__ __launch_bounds__(256)
void stencil_kernel(const float* __restrict__ offset,
                    const float* __restrict__ weight,
                    float* __restrict__ out)
{
    const int idx = blockIdx.x * 256 + threadIdx.x;   // B*(D/DCHUNK)*HW threads
    const int per_b = (D_ / DCHUNK) * HW_;
    const int b  = idx / per_b;
    const int r  = idx - b * per_b;
    const int dc = r / HW_;
    const int hw = r - dc * HW_;
    const int h  = hw / W_;
    const int w  = hw - h * W_;

    // offset weights (uniform across d)
    float wWide[9], wNar[9];
    const long obase = (long)b * 18 * HW_ + hw;
#pragma unroll
    for (int s = 0; s < 9; s++) {
        wWide[s] = __ldg(&offset[obase + (long)s * HW_]);
        wNar[s]  = __ldg(&offset[obase + (long)(s + 9) * HW_]);
    }
    const float wgt = 0.5f * __ldg(&weight[(long)b * HW_ + hw]);

    // reflected row/col indices for both scales
    int ry1[3], rx1[3], ry2[3], rx2[3];
#pragma unroll
    for (int i = 0; i < 3; i++) {
        ry1[i] = reflect_idx(h + 2 * (i - 1), H_);
        rx1[i] = reflect_idx(w + 2 * (i - 1), W_);
        ry2[i] = reflect_idx(h + 4 * (i - 1), H_);
        rx2[i] = reflect_idx(w + 4 * (i - 1), W_);
    }

    const int d0 = dc * DCHUNK;
#pragma unroll
    for (int dd = 0; dd < DCHUNK; dd++) {
        const long base_d = (long)(b * D_ + d0 + dd) * HW_;
        float acc = 0.0f;
#pragma unroll
        for (int iy = 0; iy < 3; iy++) {
            const long ro1 = base_d + (long)ry1[iy] * W_;
            const long ro2 = base_d + (long)ry2[iy] * W_;
#pragma unroll
            for (int ix = 0; ix < 3; ix++) {
                const int s = iy * 3 + ix;
                acc = fmaf(wNar[s],  g_sim[ro1 + rx1[ix]], acc);
                acc = fmaf(wWide[s], g_sim[ro2 + rx2[ix]], acc);
            }
        }
        out[base_d + hw] = acc * wgt;
    }
}

// ---------------------------------------------------------------------------
// Launch
// ---------------------------------------------------------------------------
extern "C" void kernel_launch(void* const* d_in, const int* in_sizes, int n_in,
                              void* d_out, int out_size)
{
    const float* x1        = (const float*)d_in[0];
    const float* offset    = (const float*)d_in[1];
    const float* weight    = (const float*)d_in[2];
    const float* w0        = (const float*)d_in[3];
    const float* bn0_scale = (const float*)d_in[4];
    const float* bn0_bias  = (const float*)d_in[5];
    const float* w1        = (const float*)d_in[6];
    const float* bn1_scale = (const float*)d_in[7];
    const float* bn1_bias  = (const float*)d_in[8];
    const float* w_sim     = (const float*)d_in[9];
    const float* b_sim     = (const float*)d_in[10];
    float* out = (float*)d_out;

    // Kernel 1: 1,310,720 threads
    mlp_sim_kernel<<<N1_ / 256, 256>>>(x1, w0, bn0_scale, bn0_bias,
                                       w1, bn1_scale, bn1_bias, w_sim, b_sim);

    // Kernel 2: B*(D/DCHUNK)*HW = 327,680 threads
    const int n2 = B_ * (D_ / DCHUNK) * HW_;
    stencil_kernel<<<n2 / 256, 256>>>(offset, weight, out);
}

// round 7
// speedup vs baseline: 1.1868x; 1.1868x over previous
#include <cuda_runtime.h>
#include <cuda_bf16.h>

// Problem dims (fixed by the reference):
// B=2, G=8, D=32, H=128, W=160, NEIGH=9 (3x3), PAD1=2, PAD2=4
#define B_  2
#define G_  8
#define D_  32
#define H_  128
#define W_  160
#define HW_ (H_*W_)          // 20480
#define DHW_ (D_*HW_)        // 655360
#define N1_ (B_*DHW_)        // 1310720  (sim / output elements)

typedef unsigned long long u64;

// Scratch for the per-pixel similarity map (B, D, H, W) fp32 = 5.24 MB
__device__ float g_sim[N1_];

// ---------------------------------------------------------------------------
// Packed f32x2 helpers (Blackwell sm_103a)
// ---------------------------------------------------------------------------
__device__ __forceinline__ u64 pk2(float lo, float hi) {
    u64 r; asm("mov.b64 %0, {%1, %2};" : "=l"(r) : "f"(lo), "f"(hi)); return r;
}
__device__ __forceinline__ void upk2(u64 v, float& lo, float& hi) {
    asm("mov.b64 {%0, %1}, %2;" : "=f"(lo), "=f"(hi) : "l"(v));
}
__device__ __forceinline__ u64 fma2(u64 a, u64 b, u64 c) {
    u64 d; asm("fma.rn.f32x2 %0, %1, %2, %3;" : "=l"(d) : "l"(a), "l"(b), "l"(c)); return d;
}
__device__ __forceinline__ u64 mul2(u64 a, u64 b) {
    u64 d; asm("mul.rn.f32x2 %0, %1, %2;" : "=l"(d) : "l"(a), "l"(b)); return d;
}
__device__ __forceinline__ u64 relu2(u64 v) {
    float a, b; upk2(v, a, b);
    return pk2(fmaxf(a, 0.0f), fmaxf(b, 0.0f));
}

// ---------------------------------------------------------------------------
// Kernel 1: per-pixel MLP, 4 pixels per thread, f32x2 packed math.
// sim = w_sim . relu( bn1(W1 . relu( bn0(W0 . x) )) ) + b_sim
// ---------------------------------------------------------------------------
__global__ __launch_bounds__(256)
void mlp_sim_kernel(const float* __restrict__ x1,
                    const float* __restrict__ w0,
                    const float* __restrict__ bn0_scale,
                    const float* __restrict__ bn0_bias,
                    const float* __restrict__ w1,
                    const float* __restrict__ bn1_scale,
                    const float* __restrict__ bn1_bias,
                    const float* __restrict__ w_sim,
                    const float* __restrict__ b_sim)
{
    __shared__ u64   sw0p[16*8];   // (w0[o][g]*bn0_scale[o]) duplicated into both halves
    __shared__ u64   sw1p[8*16];   // (w1[k][o]*bn1_scale[k]) duplicated
    __shared__ float sb0[16];
    __shared__ float sb1[8];
    __shared__ float sws[8];
    __shared__ float sbs;

    const int t = threadIdx.x;
    if (t < 128) {
        float v = w0[t] * bn0_scale[t >> 3];
        sw0p[t] = pk2(v, v);
    } else {
        int i = t - 128;               // 0..127
        float v = w1[i] * bn1_scale[i >> 4];
        sw1p[i] = pk2(v, v);
    }
    if (t < 16)       sb0[t] = bn0_bias[t];
    else if (t < 24)  sb1[t - 16] = bn1_bias[t - 16];
    else if (t < 32)  sws[t - 24] = w_sim[t - 24];
    else if (t == 32) sbs = b_sim[0];
    __syncthreads();

    const int idx4 = (blockIdx.x * 256 + t) * 4;     // N1_ multiple of 1024
    const int b = idx4 / DHW_;                       // 4 pixels share b (DHW_%4==0)
    // x1 flat index of (b, g=0, pixel idx4):  idx4 + b*(G-1)*DHW_
    const int base = idx4 + b * (G_ - 1) * DHW_;     // multiple of 4

    const float4* __restrict__ x4 = (const float4*)x1;

    u64 xp[2][G_];
#pragma unroll
    for (int g = 0; g < G_; g++) {
        float4 v = __ldg(&x4[(base + g * DHW_) >> 2]);
        xp[0][g] = pk2(v.x, v.y);
        xp[1][g] = pk2(v.z, v.w);
    }

    u64 h1p[2][8];
#pragma unroll
    for (int k = 0; k < 8; k++) {
        u64 bb = pk2(sb1[k], sb1[k]);
        h1p[0][k] = bb; h1p[1][k] = bb;
    }

#pragma unroll
    for (int o = 0; o < 16; o++) {
        u64 a0 = pk2(sb0[o], sb0[o]);
        u64 a1 = a0;
#pragma unroll
        for (int g = 0; g < G_; g++) {
            u64 w = sw0p[o * 8 + g];
            a0 = fma2(w, xp[0][g], a0);
            a1 = fma2(w, xp[1][g], a1);
        }
        a0 = relu2(a0);
        a1 = relu2(a1);
#pragma unroll
        for (int k = 0; k < 8; k++) {
            u64 w = sw1p[k * 16 + o];
            h1p[0][k] = fma2(w, a0, h1p[0][k]);
            h1p[1][k] = fma2(w, a1, h1p[1][k]);
        }
    }

    float s[4];
#pragma unroll
    for (int p = 0; p < 2; p++) {
        float s_lo = sbs, s_hi = sbs;
#pragma unroll
        for (int k = 0; k < 8; k++) {
            float lo, hi; upk2(h1p[p][k], lo, hi);
            s_lo = fmaf(sws[k], fmaxf(lo, 0.0f), s_lo);
            s_hi = fmaf(sws[k], fmaxf(hi, 0.0f), s_hi);
        }
        s[p * 2]     = s_lo;
        s[p * 2 + 1] = s_hi;
    }
    ((float4*)g_sim)[idx4 >> 2] = make_float4(s[0], s[1], s[2], s[3]);
}

// ---------------------------------------------------------------------------
// Kernel 2: two-scale 3x3 reflect stencil over sim, weighted by offset maps.
// One thread per (b, d-chunk of 4, h, pixel-pair (w0, w0+1)), w0 even.
// Interior threads use aligned LD.64 taps + f32x2 FMAs; edge threads scalar.
// ---------------------------------------------------------------------------
#define DCHUNK 4

__device__ __forceinline__ int reflect_idx(int k, int n) {
    if (k < 0) return -k;
    if (k >= n) return 2 * n - 2 - k;
    return k;
}

__global__ __launch_bounds__(256)
void stencil_kernel(const float* __restrict__ offset,
                    const float* __restrict__ weight,
                    float* __restrict__ out)
{
    const int idx = blockIdx.x * 256 + threadIdx.x;   // B*(D/DCHUNK)*H*(W/2)
    const int per_b = (D_ / DCHUNK) * H_ * (W_ / 2);  // 81920
    const int b  = idx / per_b;
    int r        = idx - b * per_b;
    const int dc = r / (H_ * (W_ / 2));
    r           -= dc * (H_ * (W_ / 2));
    const int h  = r / (W_ / 2);
    const int w0 = (r - h * (W_ / 2)) * 2;
    const int hw = h * W_ + w0;

    // per-pixel-pair offset weights, packed (lane0=w0, lane1=w0+1)
    const u64* __restrict__ off64 = (const u64*)offset;
    u64 wW2[9], wN2[9];
    const int obase = b * 18 * HW_ + hw;              // even
#pragma unroll
    for (int s = 0; s < 9; s++) {
        wW2[s] = __ldg(&off64[(obase + s * HW_) >> 1]);
        wN2[s] = __ldg(&off64[(obase + (s + 9) * HW_) >> 1]);
    }
    u64 wgt2;
    {
        float g0, g1;
        upk2(__ldg(&((const u64*)weight)[(b * HW_ + hw) >> 1]), g0, g1);
        wgt2 = pk2(0.5f * g0, 0.5f * g1);
    }

    // reflected rows (vertical reflect never breaks pair contiguity)
    int ry1[3], ry2[3];
#pragma unroll
    for (int i = 0; i < 3; i++) {
        ry1[i] = reflect_idx(h + 2 * (i - 1), H_);
        ry2[i] = reflect_idx(h + 4 * (i - 1), H_);
    }

    const int d0 = (b * D_ + dc * DCHUNK) * HW_;
    const u64* __restrict__ sim64 = (const u64*)g_sim;
    u64* __restrict__ out64 = (u64*)out;

    const bool interior = (w0 >= 4) && (w0 <= W_ - 6);

    if (interior) {
        // hoisted tap offsets in u64 units, invariant across dd
        int off1[9], off2[9];
#pragma unroll
        for (int iy = 0; iy < 3; iy++) {
#pragma unroll
            for (int ix = 0; ix < 3; ix++) {
                const int s = iy * 3 + ix;
                off1[s] = (ry1[iy] * W_ + w0 + 2 * (ix - 1)) >> 1;
                off2[s] = (ry2[iy] * W_ + w0 + 4 * (ix - 1)) >> 1;
            }
        }
        const u64* __restrict__ simb = sim64 + (d0 >> 1);
#pragma unroll
        for (int dd = 0; dd < DCHUNK; dd++) {
            const u64* __restrict__ p = simb + dd * (HW_ / 2);
            u64 acc = 0ULL;
#pragma unroll
            for (int s = 0; s < 9; s++) {
                acc = fma2(wN2[s], p[off1[s]], acc);
                acc = fma2(wW2[s], p[off2[s]], acc);
            }
            out64[((d0 + dd * HW_) + hw) >> 1] = mul2(acc, wgt2);
        }
    } else {
        // edge path: scalar reflect in x for both pixels of the pair
        int rx1a[3], rx2a[3], rx1b[3], rx2b[3];
#pragma unroll
        for (int i = 0; i < 3; i++) {
            rx1a[i] = reflect_idx(w0     + 2 * (i - 1), W_);
            rx2a[i] = reflect_idx(w0     + 4 * (i - 1), W_);
            rx1b[i] = reflect_idx(w0 + 1 + 2 * (i - 1), W_);
            rx2b[i] = reflect_idx(w0 + 1 + 4 * (i - 1), W_);
        }
#pragma unroll
        for (int dd = 0; dd < DCHUNK; dd++) {
            const int bd = d0 + dd * HW_;
            float acc0 = 0.0f, acc1 = 0.0f;
#pragma unroll
            for (int iy = 0; iy < 3; iy++) {
                const int ro1 = bd + ry1[iy] * W_;
                const int ro2 = bd + ry2[iy] * W_;
#pragma unroll
                for (int ix = 0; ix < 3; ix++) {
                    const int s = iy * 3 + ix;
                    float n0, n1, wv0, wv1;
                    upk2(wN2[s], n0, n1);
                    upk2(wW2[s], wv0, wv1);
                    acc0 = fmaf(n0,  g_sim[ro1 + rx1a[ix]], acc0);
                    acc0 = fmaf(wv0, g_sim[ro2 + rx2a[ix]], acc0);
                    acc1 = fmaf(n1,  g_sim[ro1 + rx1b[ix]], acc1);
                    acc1 = fmaf(wv1, g_sim[ro2 + rx2b[ix]], acc1);
                }
            }
            out64[(bd + hw) >> 1] = mul2(pk2(acc0, acc1), wgt2);
        }
    }
}

// ---------------------------------------------------------------------------
// Launch
// ---------------------------------------------------------------------------
extern "C" void kernel_launch(void* const* d_in, const int* in_sizes, int n_in,
                              void* d_out, int out_size)
{
    const float* x1        = (const float*)d_in[0];
    const float* offset    = (const float*)d_in[1];
    const float* weight    = (const float*)d_in[2];
    const float* w0        = (const float*)d_in[3];
    const float* bn0_scale = (const float*)d_in[4];
    const float* bn0_bias  = (const float*)d_in[5];
    const float* w1        = (const float*)d_in[6];
    const float* bn1_scale = (const float*)d_in[7];
    const float* bn1_bias  = (const float*)d_in[8];
    const float* w_sim     = (const float*)d_in[9];
    const float* b_sim     = (const float*)d_in[10];
    float* out = (float*)d_out;

    // Kernel 1: 4 pixels/thread -> 327,680 threads
    mlp_sim_kernel<<<N1_ / (256 * 4), 256>>>(x1, w0, bn0_scale, bn0_bias,
                                             w1, bn1_scale, bn1_bias, w_sim, b_sim);

    // Kernel 2: pixel-pair threads: B*(D/4)*H*(W/2) = 163,840
    const int n2 = B_ * (D_ / DCHUNK) * H_ * (W_ / 2);
    stencil_kernel<<<n2 / 256, 256>>>(offset, weight, out);
}

// round 8
// speedup vs baseline: 1.2500x; 1.0533x over previous
#include <cuda_runtime.h>
#include <cuda_bf16.h>

// Problem dims (fixed by the reference):
// B=2, G=8, D=32, H=128, W=160, NEIGH=9 (3x3), PAD1=2, PAD2=4
#define B_  2
#define G_  8
#define D_  32
#define H_  128
#define W_  160
#define HW_ (H_*W_)          // 20480
#define DHW_ (D_*HW_)        // 655360
#define N1_ (B_*DHW_)        // 1310720  (sim / output elements)

typedef unsigned long long u64;

// Scratch for the per-pixel similarity map (B, D, H, W) fp32 = 5.24 MB
__device__ float g_sim[N1_];

// ---------------------------------------------------------------------------
// Packed f32x2 helpers (Blackwell sm_103a)
// ---------------------------------------------------------------------------
__device__ __forceinline__ u64 pk2(float lo, float hi) {
    u64 r; asm("mov.b64 %0, {%1, %2};" : "=l"(r) : "f"(lo), "f"(hi)); return r;
}
__device__ __forceinline__ void upk2(u64 v, float& lo, float& hi) {
    asm("mov.b64 {%0, %1}, %2;" : "=f"(lo), "=f"(hi) : "l"(v));
}
__device__ __forceinline__ u64 fma2(u64 a, u64 b, u64 c) {
    u64 d; asm("fma.rn.f32x2 %0, %1, %2, %3;" : "=l"(d) : "l"(a), "l"(b), "l"(c)); return d;
}
__device__ __forceinline__ u64 mul2(u64 a, u64 b) {
    u64 d; asm("mul.rn.f32x2 %0, %1, %2;" : "=l"(d) : "l"(a), "l"(b)); return d;
}
__device__ __forceinline__ u64 relu2(u64 v) {
    float a, b; upk2(v, a, b);
    return pk2(fmaxf(a, 0.0f), fmaxf(b, 0.0f));
}

// ---------------------------------------------------------------------------
// Kernel 1: per-pixel MLP, 4 pixels per thread, f32x2 packed math.
// Weight pairs fetched with one LDS.128 each (halves shared-load issue).
// sim = w_sim . relu( bn1(W1 . relu( bn0(W0 . x) )) ) + b_sim
// ---------------------------------------------------------------------------
__global__ __launch_bounds__(256)
void mlp_sim_kernel(const float* __restrict__ x1,
                    const float* __restrict__ w0,
                    const float* __restrict__ bn0_scale,
                    const float* __restrict__ bn0_bias,
                    const float* __restrict__ w1,
                    const float* __restrict__ bn1_scale,
                    const float* __restrict__ bn1_bias,
                    const float* __restrict__ w_sim,
                    const float* __restrict__ b_sim)
{
    // sw0p[o*8+g]  = dup2( w0[o][g]  * bn0_scale[o] )   (g contiguous)
    // sw1p[o*8+k]  = dup2( w1[k][o]  * bn1_scale[k] )   (k contiguous)
    __shared__ __align__(16) u64 sw0p[16*8];
    __shared__ __align__(16) u64 sw1p[16*8];
    __shared__ float sb0[16];
    __shared__ float sb1[8];
    __shared__ float sws[8];
    __shared__ float sbs;

    const int t = threadIdx.x;
    if (t < 128) {
        float v = w0[t] * bn0_scale[t >> 3];     // t = o*8+g
        sw0p[t] = pk2(v, v);
    } else {
        int i = t - 128;                         // i = o*8+k
        int o = i >> 3, k = i & 7;
        float v = w1[k * 16 + o] * bn1_scale[k];
        sw1p[i] = pk2(v, v);
    }
    if (t < 16)       sb0[t] = bn0_bias[t];
    else if (t < 24)  sb1[t - 16] = bn1_bias[t - 16];
    else if (t < 32)  sws[t - 24] = w_sim[t - 24];
    else if (t == 32) sbs = b_sim[0];
    __syncthreads();

    const int idx4 = (blockIdx.x * 256 + t) * 4;     // N1_ multiple of 1024
    const int b = idx4 / DHW_;                       // 4 pixels share b (DHW_%4==0)
    const int base = idx4 + b * (G_ - 1) * DHW_;     // x1 flat idx of (b,g=0,pix)

    const float4* __restrict__ x4 = (const float4*)x1;

    u64 xp[2][G_];
#pragma unroll
    for (int g = 0; g < G_; g++) {
        float4 v = __ldg(&x4[(base + g * DHW_) >> 2]);
        xp[0][g] = pk2(v.x, v.y);
        xp[1][g] = pk2(v.z, v.w);
    }

    u64 h1p[2][8];
#pragma unroll
    for (int k = 0; k < 8; k++) {
        u64 bb = pk2(sb1[k], sb1[k]);
        h1p[0][k] = bb; h1p[1][k] = bb;
    }

#pragma unroll
    for (int o = 0; o < 16; o++) {
        u64 a0 = pk2(sb0[o], sb0[o]);
        u64 a1 = a0;
#pragma unroll
        for (int g = 0; g < G_; g += 2) {
            ulonglong2 wv = *(const ulonglong2*)&sw0p[o * 8 + g];  // LDS.128
            a0 = fma2(wv.x, xp[0][g],     a0);
            a1 = fma2(wv.x, xp[1][g],     a1);
            a0 = fma2(wv.y, xp[0][g + 1], a0);
            a1 = fma2(wv.y, xp[1][g + 1], a1);
        }
        a0 = relu2(a0);
        a1 = relu2(a1);
#pragma unroll
        for (int k = 0; k < 8; k += 2) {
            ulonglong2 wv = *(const ulonglong2*)&sw1p[o * 8 + k];  // LDS.128
            h1p[0][k]     = fma2(wv.x, a0, h1p[0][k]);
            h1p[1][k]     = fma2(wv.x, a1, h1p[1][k]);
            h1p[0][k + 1] = fma2(wv.y, a0, h1p[0][k + 1]);
            h1p[1][k + 1] = fma2(wv.y, a1, h1p[1][k + 1]);
        }
    }

    float s[4];
#pragma unroll
    for (int p = 0; p < 2; p++) {
        float s_lo = sbs, s_hi = sbs;
#pragma unroll
        for (int k = 0; k < 8; k++) {
            float lo, hi; upk2(h1p[p][k], lo, hi);
            s_lo = fmaf(sws[k], fmaxf(lo, 0.0f), s_lo);
            s_hi = fmaf(sws[k], fmaxf(hi, 0.0f), s_hi);
        }
        s[p * 2]     = s_lo;
        s[p * 2 + 1] = s_hi;
    }
    ((float4*)g_sim)[idx4 >> 2] = make_float4(s[0], s[1], s[2], s[3]);
}

// ---------------------------------------------------------------------------
// Kernel 2: two-scale 3x3 reflect stencil over sim, weighted by offset maps.
// One thread per (b, d-chunk of 4, h, pixel-pair (w0, w0+1)), w0 even.
// iy loop NOT unrolled -> nothing large stays live -> low regs, high occupancy.
// ---------------------------------------------------------------------------
#define DCHUNK 4

__device__ __forceinline__ int reflect_idx(int k, int n) {
    if (k < 0) return -k;
    if (k >= n) return 2 * n - 2 - k;
    return k;
}

__global__ __launch_bounds__(128)
void stencil_kernel(const float* __restrict__ offset,
                    const float* __restrict__ weight,
                    float* __restrict__ out)
{
    const int idx = blockIdx.x * 128 + threadIdx.x;   // B*(D/DCHUNK)*H*(W/2)
    const int per_b = (D_ / DCHUNK) * H_ * (W_ / 2);  // 81920
    const int b  = idx / per_b;
    int r        = idx - b * per_b;
    const int dc = r / (H_ * (W_ / 2));
    r           -= dc * (H_ * (W_ / 2));
    const int h  = r / (W_ / 2);
    const int w0 = (r - h * (W_ / 2)) * 2;
    const int hw = h * W_ + w0;

    const u64* __restrict__ off64 = (const u64*)offset;
    const int obase = (b * 18 * HW_ + hw) >> 1;       // u64 index (hw even)

    u64 wgt2;
    {
        float g0, g1;
        upk2(__ldg(&((const u64*)weight)[(b * HW_ + hw) >> 1]), g0, g1);
        wgt2 = pk2(0.5f * g0, 0.5f * g1);
    }

    const int d0 = (b * D_ + dc * DCHUNK) * HW_;
    const u64* __restrict__ simb = (const u64*)g_sim + (d0 >> 1);
    u64* __restrict__ out64 = (u64*)out;

    u64 acc[DCHUNK];
#pragma unroll
    for (int dd = 0; dd < DCHUNK; dd++) acc[dd] = 0ULL;

    const bool interior = (w0 >= 4) && (w0 <= W_ - 6);

    if (interior) {
#pragma unroll 1
        for (int iy = 0; iy < 3; iy++) {
            const int ry1 = reflect_idx(h + 2 * (iy - 1), H_);
            const int ry2 = reflect_idx(h + 4 * (iy - 1), H_);
            const int r1 = (ry1 * W_ + w0) >> 1;      // u64 index of center tap
            const int r2 = (ry2 * W_ + w0) >> 1;
#pragma unroll
            for (int ix = 0; ix < 3; ix++) {
                const int s = iy * 3 + ix;
                const u64 wW = __ldg(&off64[obase + s * (HW_ / 2)]);
                const u64 wN = __ldg(&off64[obase + (s + 9) * (HW_ / 2)]);
#pragma unroll
                for (int dd = 0; dd < DCHUNK; dd++) {
                    const u64* __restrict__ p = simb + dd * (HW_ / 2);
                    acc[dd] = fma2(wN, p[r1 + (ix - 1)],     acc[dd]);
                    acc[dd] = fma2(wW, p[r2 + 2 * (ix - 1)], acc[dd]);
                }
            }
        }
    } else {
        // edge path: scalar reflect in x for both pixels of the pair
        float a0[DCHUNK], a1[DCHUNK];
#pragma unroll
        for (int dd = 0; dd < DCHUNK; dd++) { a0[dd] = 0.0f; a1[dd] = 0.0f; }
#pragma unroll 1
        for (int iy = 0; iy < 3; iy++) {
            const int ro1 = reflect_idx(h + 2 * (iy - 1), H_) * W_;
            const int ro2 = reflect_idx(h + 4 * (iy - 1), H_) * W_;
#pragma unroll
            for (int ix = 0; ix < 3; ix++) {
                const int s = iy * 3 + ix;
                float wW0, wW1, wN0, wN1;
                upk2(__ldg(&off64[obase + s * (HW_ / 2)]), wW0, wW1);
                upk2(__ldg(&off64[obase + (s + 9) * (HW_ / 2)]), wN0, wN1);
                const int x1a = reflect_idx(w0     + 2 * (ix - 1), W_);
                const int x1b = reflect_idx(w0 + 1 + 2 * (ix - 1), W_);
                const int x2a = reflect_idx(w0     + 4 * (ix - 1), W_);
                const int x2b = reflect_idx(w0 + 1 + 4 * (ix - 1), W_);
#pragma unroll
                for (int dd = 0; dd < DCHUNK; dd++) {
                    const float* __restrict__ ps = g_sim + d0 + dd * HW_;
                    a0[dd] = fmaf(wN0, ps[ro1 + x1a], a0[dd]);
                    a0[dd] = fmaf(wW0, ps[ro2 + x2a], a0[dd]);
                    a1[dd] = fmaf(wN1, ps[ro1 + x1b], a1[dd]);
                    a1[dd] = fmaf(wW1, ps[ro2 + x2b], a1[dd]);
                }
            }
        }
#pragma unroll
        for (int dd = 0; dd < DCHUNK; dd++) acc[dd] = pk2(a0[dd], a1[dd]);
    }

#pragma unroll
    for (int dd = 0; dd < DCHUNK; dd++)
        out64[(d0 + dd * HW_ + hw) >> 1] = mul2(acc[dd], wgt2);
}

// ---------------------------------------------------------------------------
// Launch
// ---------------------------------------------------------------------------
extern "C" void kernel_launch(void* const* d_in, const int* in_sizes, int n_in,
                              void* d_out, int out_size)
{
    const float* x1        = (const float*)d_in[0];
    const float* offset    = (const float*)d_in[1];
    const float* weight    = (const float*)d_in[2];
    const float* w0        = (const float*)d_in[3];
    const float* bn0_scale = (const float*)d_in[4];
    const float* bn0_bias  = (const float*)d_in[5];
    const float* w1        = (const float*)d_in[6];
    const float* bn1_scale = (const float*)d_in[7];
    const float* bn1_bias  = (const float*)d_in[8];
    const float* w_sim     = (const float*)d_in[9];
    const float* b_sim     = (const float*)d_in[10];
    float* out = (float*)d_out;

    // Kernel 1: 4 pixels/thread -> 327,680 threads, grid 1280
    mlp_sim_kernel<<<N1_ / (256 * 4), 256>>>(x1, w0, bn0_scale, bn0_bias,
                                             w1, bn1_scale, bn1_bias, w_sim, b_sim);

    // Kernel 2: pixel-pair threads: B*(D/4)*H*(W/2) = 163,840, grid 1280
    const int n2 = B_ * (D_ / DCHUNK) * H_ * (W_ / 2);
    stencil_kernel<<<n2 / 128, 128>>>(offset, weight, out);
}